// round 17
// baseline (speedup 1.0000x reference)
#include <cuda_runtime.h>
#include <cuda_fp16.h>
#include <cstdint>

// Router: logits = x@W + b (N=16384, D=2048, E=64), softmax, top-2, aux loss.
// fp16 m16n8k16 mma 3-pass (rn hi/lo split, residual scaled 2^12).
// Tiles pre-split at stage time into INTERLEAVED (hi,lo) u32 smem; mainloop is
// pure vector LDS.64 -> MMA (zero converts on the critical path).
// Split accumulators + per-chunk drain of hh into FFMA fp32 sums.
// Finalize folded into main kernel (last-block threadfence reduction).
// Output layout (float32): [weights N*2][indices-as-float N*2][aux 1]

#define DDIM   2048
#define EDIM   64
#define BM     128
#define BK     32
#define NCHUNK (DDIM / BK)      // 64
#define NTHREADS 256

#define APITCH 40               // u32 per A row (32 used): LDS.64 banks 8g+2tg, distinct
#define BPITCH 136              // u32 per B pair-row (128 used): banks 8tg+2g, distinct

// u32-indexed tile layout
#define A_U       0                          // 128 x 40 = 5120
#define B_U       5120                       // 16 x 136 = 2176 -> 7296
// float-indexed epilogue layout (reuses tile region)
#define LG_OFF    0                          // 128 x 65 = 8320
#define LG_STRIDE 65
#define BIAS_OFF  8320                       // 64 floats (also reduce buf)
#define CNT_OFF   8384                       // 64 ints
#define SMEM_FLOATS 8448                     // 33792 bytes

#define RSCALE   4096.0f
#define RSCALE_I (1.0f / 4096.0f)

__device__ float g_cnt[EDIM];
__device__ float g_prob[EDIM];
__device__ unsigned g_done;

__global__ void zero_acc_kernel() {
    int t = threadIdx.x;
    if (t < EDIM) { g_cnt[t] = 0.0f; g_prob[t] = 0.0f; }
    if (t == 0) g_done = 0u;
}

__device__ __forceinline__ void mma16h(float d[4],
                                       uint32_t a0, uint32_t a1, uint32_t a2, uint32_t a3,
                                       uint32_t b0, uint32_t b1) {
    asm volatile(
        "mma.sync.aligned.m16n8k16.row.col.f32.f16.f16.f32 "
        "{%0,%1,%2,%3}, {%4,%5,%6,%7}, {%8,%9}, {%0,%1,%2,%3};"
        : "+f"(d[0]), "+f"(d[1]), "+f"(d[2]), "+f"(d[3])
        : "r"(a0), "r"(a1), "r"(a2), "r"(a3), "r"(b0), "r"(b1));
}

// (v0,v1) -> hi f16x2 (rn; low half = v0) and scaled-residual f16x2.
__device__ __forceinline__ void prep2(float v0, float v1, uint32_t& hi, uint32_t& lo) {
    __half h0 = __float2half_rn(v0);
    __half h1 = __float2half_rn(v1);
    __half2 hp = __halves2half2(h0, h1);
    hi = *reinterpret_cast<uint32_t*>(&hp);
    float r0 = (v0 - __half2float(h0)) * RSCALE;
    float r1 = (v1 - __half2float(h1)) * RSCALE;
    __half2 lp = __floats2half2_rn(r0, r1);
    lo = *reinterpret_cast<uint32_t*>(&lp);
}

__global__ void __launch_bounds__(NTHREADS)
router_main_kernel(const float* __restrict__ x,
                   const float* __restrict__ W,
                   const float* __restrict__ b,
                   float* __restrict__ out, int N)
{
    __shared__ float sm[SMEM_FLOATS];
    __shared__ int is_last;
    uint32_t* su = reinterpret_cast<uint32_t*>(sm);
    const int tid  = threadIdx.x;
    const int lane = tid & 31;
    const int wid  = tid >> 5;          // 0..7: tokens [16*wid, +16)
    const int g    = lane >> 2;         // 0..7
    const int tg   = lane & 3;          // 0..3
    const int row0 = blockIdx.x * BM;

    // fixed per-thread staging coordinates (hoisted)
    const int ar0 = tid >> 3;                 // A rows for j=0..3: ar0 + 32j
    const int aq  = tid & 7;                  // A float4 column
    const int bp0 = tid >> 6;                 // B pairs for j=0..3: bp0 + 4j
    const int be  = tid & 63;                 // B expert

    float sum[8][4];     // FFMA-maintained hh sums (unbiased)
    float acc[8][4];     // TC hh accumulator, drained each chunk
    float cor[8][4];     // TC correction accumulator (scaled by RSCALE)
    #pragma unroll
    for (int nf = 0; nf < 8; nf++)
        #pragma unroll
        for (int i = 0; i < 4; i++) {
            sum[nf][i] = 0.0f; acc[nf][i] = 0.0f; cor[nf][i] = 0.0f;
        }

    // ---- prefetch chunk 0 ----
    float4 a4[4]; float bw0[4], bw1[4];
    {
        const float* xp = x + (size_t)row0 * DDIM;
        #pragma unroll
        for (int j = 0; j < 4; j++)
            a4[j] = *(const float4*)(xp + (size_t)(ar0 + 32 * j) * DDIM + (aq << 2));
        #pragma unroll
        for (int j = 0; j < 4; j++) {
            int p = bp0 + 4 * j;
            bw0[j] = W[(size_t)(2 * p) * EDIM + be];
            bw1[j] = W[(size_t)(2 * p + 1) * EDIM + be];
        }
    }

    for (int c = 0; c < NCHUNK; c++) {
        // ---- stage chunk c: split once, store interleaved (h,l) ----
        #pragma unroll
        for (int j = 0; j < 4; j++) {
            uint32_t h0, l0, h1, l1;
            prep2(a4[j].x, a4[j].y, h0, l0);
            prep2(a4[j].z, a4[j].w, h1, l1);
            uint4 v = make_uint4(h0, l0, h1, l1);
            *(uint4*)(su + A_U + (ar0 + 32 * j) * APITCH + (aq << 2)) = v;
        }
        #pragma unroll
        for (int j = 0; j < 4; j++) {
            uint32_t h, l;
            prep2(bw0[j], bw1[j], h, l);
            uint2 v = make_uint2(h, l);
            *(uint2*)(su + B_U + (bp0 + 4 * j) * BPITCH + (be << 1)) = v;
        }
        __syncthreads();

        // ---- issue global loads for chunk c+1 (overlap with MMAs) ----
        if (c + 1 < NCHUNK) {
            const int k0 = (c + 1) * BK;
            const float* xp = x + (size_t)row0 * DDIM + k0;
            #pragma unroll
            for (int j = 0; j < 4; j++)
                a4[j] = *(const float4*)(xp + (size_t)(ar0 + 32 * j) * DDIM + (aq << 2));
            #pragma unroll
            for (int j = 0; j < 4; j++) {
                int p = bp0 + 4 * j;
                bw0[j] = W[(size_t)(k0 + 2 * p) * EDIM + be];
                bw1[j] = W[(size_t)(k0 + 2 * p + 1) * EDIM + be];
            }
        }

        // ---- compute chunk c: two k16 halves, pure LDS.64 + MMA ----
        #pragma unroll
        for (int j = 0; j < 2; j++) {
            const int pb = (j << 3) + tg;      // pair base; +4 for second half

            int r0 = (wid << 4) + g;
            int r1 = r0 + 8;
            uint2 a0 = *(const uint2*)(su + A_U + r0 * APITCH + (pb << 1));
            uint2 a1 = *(const uint2*)(su + A_U + r1 * APITCH + (pb << 1));
            uint2 a2 = *(const uint2*)(su + A_U + r0 * APITCH + ((pb + 4) << 1));
            uint2 a3 = *(const uint2*)(su + A_U + r1 * APITCH + ((pb + 4) << 1));

            #pragma unroll
            for (int nf = 0; nf < 8; nf++) {
                int e2 = ((nf << 3) + g) << 1;
                uint2 b0 = *(const uint2*)(su + B_U + pb * BPITCH + e2);
                uint2 b1 = *(const uint2*)(su + B_U + (pb + 4) * BPITCH + e2);
                mma16h(acc[nf], a0.x, a1.x, a2.x, a3.x, b0.x, b1.x);
                mma16h(cor[nf], a0.x, a1.x, a2.x, a3.x, b0.y, b1.y);
                mma16h(cor[nf], a0.y, a1.y, a2.y, a3.y, b0.x, b1.x);
            }
        }

        // ---- drain hh accumulator into FFMA sums ----
        #pragma unroll
        for (int nf = 0; nf < 8; nf++)
            #pragma unroll
            for (int i = 0; i < 4; i++) {
                sum[nf][i] += acc[nf][i];
                acc[nf][i] = 0.0f;
            }

        __syncthreads();
    }

    // ---- bias/cnt init ----
    if (tid < EDIM) {
        sm[BIAS_OFF + tid] = b[tid];
        ((int*)sm)[CNT_OFF + tid] = 0;
    }

    // ---- spill logits (sum + unscaled correction) to smem ----
    {
        float* lg = sm + LG_OFF;
        int t = (wid << 4) + g;
        #pragma unroll
        for (int nf = 0; nf < 8; nf++) {
            int e = (nf << 3) + (tg << 1);
            lg[t * LG_STRIDE + e]           = sum[nf][0] + cor[nf][0] * RSCALE_I;
            lg[t * LG_STRIDE + e + 1]       = sum[nf][1] + cor[nf][1] * RSCALE_I;
            lg[(t + 8) * LG_STRIDE + e]     = sum[nf][2] + cor[nf][2] * RSCALE_I;
            lg[(t + 8) * LG_STRIDE + e + 1] = sum[nf][3] + cor[nf][3] * RSCALE_I;
        }
    }
    __syncthreads();

    // ---- per-token: bias + top-2 + softmax + outputs ----
    if (tid < BM) {
        const int m = tid;
        float lg[EDIM];
        #pragma unroll
        for (int e = 0; e < EDIM; e++)
            lg[e] = sm[LG_OFF + m * LG_STRIDE + e] + sm[BIAS_OFF + e];

        float v1 = -3.0e38f, v2 = -3.0e38f;
        int i1 = 0, i2 = 0;
        #pragma unroll
        for (int e = 0; e < EDIM; e++) {
            float l = lg[e];
            if (l > v1)      { v2 = v1; i2 = i1; v1 = l; i1 = e; }
            else if (l > v2) { v2 = l; i2 = e; }
        }
        float s = 0.0f;
        #pragma unroll
        for (int e = 0; e < EDIM; e++) s += __expf(lg[e] - v1);
        float inv = 1.0f / s;

        int gt = row0 + m;
        out[2 * gt + 0] = inv;
        out[2 * gt + 1] = __expf(v2 - v1) * inv;
        float* oi = out + 2 * (size_t)N;
        oi[2 * gt + 0] = (float)i1;
        oi[2 * gt + 1] = (float)i2;

        atomicAdd((int*)sm + CNT_OFF + i1, 1);
        atomicAdd((int*)sm + CNT_OFF + i2, 1);

        #pragma unroll
        for (int e = 0; e < EDIM; e++)
            sm[LG_OFF + m * LG_STRIDE + e] = __expf(lg[e] - v1) * inv;
    }
    __syncthreads();

    // ---- per-expert prob sums + global accumulation ----
    if (tid < EDIM) {
        float s = 0.0f;
        #pragma unroll 8
        for (int m = 0; m < BM; m++)
            s += sm[LG_OFF + m * LG_STRIDE + tid];
        atomicAdd(&g_prob[tid], s);
        atomicAdd(&g_cnt[tid], (float)(((int*)sm)[CNT_OFF + tid]));
        __threadfence();   // release this block's adds
    }
    __syncthreads();

    // ---- last-block finalize (threadfence reduction) ----
    if (tid == 0) {
        unsigned old = atomicAdd(&g_done, 1u);
        is_last = (old == (unsigned)(gridDim.x - 1)) ? 1 : 0;
    }
    __syncthreads();
    if (is_last) {
        __threadfence();   // acquire
        if (tid < EDIM) {
            float cv = *(volatile float*)&g_cnt[tid];
            float pv = *(volatile float*)&g_prob[tid];
            float invN = 1.0f / (float)N;
            sm[BIAS_OFF + tid] = (cv * invN) * (pv * invN);
        }
        __syncthreads();
        if (tid < 32) {
            float s = sm[BIAS_OFF + tid] + sm[BIAS_OFF + tid + 32];
            #pragma unroll
            for (int o = 16; o > 0; o >>= 1)
                s += __shfl_down_sync(0xffffffffu, s, o);
            if (tid == 0) out[4 * (size_t)N] = (float)EDIM * s;
        }
    }
}

extern "C" void kernel_launch(void* const* d_in, const int* in_sizes, int n_in,
                              void* d_out, int out_size) {
    const float* x = (const float*)d_in[0];
    const float* W = (const float*)d_in[1];
    const float* b = (const float*)d_in[2];
    int N = in_sizes[0] / DDIM;   // 16384

    float* out = (float*)d_out;
    zero_acc_kernel<<<1, 64>>>();
    router_main_kernel<<<N / BM, NTHREADS>>>(x, W, b, out, N);
}